// round 4
// baseline (speedup 1.0000x reference)
#include <cuda_runtime.h>
#include <cstdint>

#define SLOPE 0.2f
#define THREADS 128

typedef unsigned long long u64;

// ---------------- packed f32x2 helpers (Blackwell FFMA2 path) ----------------
__device__ __forceinline__ u64 fma2(u64 a, u64 b, u64 c) {
    u64 d;
    asm("fma.rn.f32x2 %0, %1, %2, %3;" : "=l"(d) : "l"(a), "l"(b), "l"(c));
    return d;
}
__device__ __forceinline__ u64 dup2(float x) {
    u64 d;
    asm("mov.b64 %0, {%1, %1};" : "=l"(d) : "f"(x));
    return d;
}
__device__ __forceinline__ float2 unpack2(u64 v) {
    float2 r;
    asm("mov.b64 {%0, %1}, %2;" : "=f"(r.x), "=f"(r.y) : "l"(v));
    return r;
}

// ---------------- shared memory layout (float offsets) ----------------
// Weights transposed: Wt[k*128 + h] = W[h][k]
#define OFF_W1   0                       // [65][128]
#define OFF_W2   (65*128)                // [128][128]
#define OFF_W3   (OFF_W2 + 128*128)      // [128][128]
#define OFF_B1   (OFF_W3 + 128*128)
#define OFF_B2   (OFF_B1 + 128)
#define OFF_B3   (OFF_B2 + 128)
#define OFF_W4   (OFF_B3 + 128)
#define OFF_BA0  (OFF_W4 + 128)          // [128][32] activation ping
#define OFF_BD0  (OFF_BA0 + 128*32)      // [128][32] deriv ping
#define OFF_BA1  (OFF_BD0 + 128*32)      // [128][32] activation pong (aliases x-tile & reduce scratch)
#define OFF_BD1  (OFF_BA1 + 128*32)      // [128][32] deriv pong
#define SMEM_FLOATS (OFF_BD1 + 128*32)   // 57,984 floats = 231,936 B  (< 232,448 cap)

// deterministic cross-d logdet partials: scratch[d][n]
__device__ float g_scratch[64 * 4096];

// Fused forward + derivative GEMM over one layer:
//   accA[h] = sum_k Wt[k][h] * Ain[k][m]      (then p = accA + b, s = slope(p))
//   accD[h] = sum_k Wt[k][h] * Din[k][m]      (then Dout = s * accD, Aout = p*s)
__device__ __forceinline__ void gemm_fused(
    float* sm, int offAin, int offDin, int offW, int offB,
    int offAout, int offDout, int m0, int h0)
{
    u64 accA[4][4], accD[4][4];
#pragma unroll
    for (int i = 0; i < 4; i++)
#pragma unroll
        for (int j = 0; j < 4; j++) { accA[i][j] = 0ull; accD[i][j] = 0ull; }

    const float* Ain = sm + offAin;
    const float* Din = sm + offDin;
    const float* Wt  = sm + offW;

#pragma unroll 2
    for (int k = 0; k < 128; k++) {
        float4 av = *(const float4*)(Ain + k * 32 + m0);
        float4 dv = *(const float4*)(Din + k * 32 + m0);
        ulonglong2 wA = *(const ulonglong2*)(Wt + k * 128 + h0);
        ulonglong2 wB = *(const ulonglong2*)(Wt + k * 128 + h0 + 4);
        u64 w[4]  = { wA.x, wA.y, wB.x, wB.y };
        u64 a[4]  = { dup2(av.x), dup2(av.y), dup2(av.z), dup2(av.w) };
        u64 dd[4] = { dup2(dv.x), dup2(dv.y), dup2(dv.z), dup2(dv.w) };
#pragma unroll
        for (int m = 0; m < 4; m++)
#pragma unroll
            for (int hp = 0; hp < 4; hp++) {
                accA[m][hp] = fma2(a[m],  w[hp], accA[m][hp]);
                accD[m][hp] = fma2(dd[m], w[hp], accD[m][hp]);
            }
    }

    float* Aout = sm + offAout;
    float* Dout = sm + offDout;
#pragma unroll
    for (int hp = 0; hp < 4; hp++) {
        const int hlo = h0 + 2 * hp, hhi = hlo + 1;
        const float blo = sm[offB + hlo];
        const float bhi = sm[offB + hhi];
        float alo[4], ahi[4], dlo[4], dhi[4];
#pragma unroll
        for (int m = 0; m < 4; m++) {
            float2 pa = unpack2(accA[m][hp]);
            float2 pd = unpack2(accD[m][hp]);
            float p0 = pa.x + blo; float s0 = (p0 > 0.f) ? 1.f : SLOPE;
            alo[m] = p0 * s0;  dlo[m] = s0 * pd.x;
            float p1 = pa.y + bhi; float s1 = (p1 > 0.f) ? 1.f : SLOPE;
            ahi[m] = p1 * s1;  dhi[m] = s1 * pd.y;
        }
        *(float4*)(Aout + hlo * 32 + m0) = make_float4(alo[0], alo[1], alo[2], alo[3]);
        *(float4*)(Aout + hhi * 32 + m0) = make_float4(ahi[0], ahi[1], ahi[2], ahi[3]);
        *(float4*)(Dout + hlo * 32 + m0) = make_float4(dlo[0], dlo[1], dlo[2], dlo[3]);
        *(float4*)(Dout + hhi * 32 + m0) = make_float4(dhi[0], dhi[1], dhi[2], dhi[3]);
    }
}

__global__ void __launch_bounds__(THREADS, 1)
npt_kernel(const float* __restrict__ x,
           const float* __restrict__ W1, const float* __restrict__ b1,
           const float* __restrict__ W2, const float* __restrict__ b2,
           const float* __restrict__ W3, const float* __restrict__ b3,
           const float* __restrict__ W4, const float* __restrict__ b4,
           float* __restrict__ out_res)
{
    extern __shared__ float sm[];
    const int tid  = threadIdx.x;
    const int d    = blockIdx.x >> 1;   // latent index
    const int half = blockIdx.x & 1;    // sample half [0..2048) / [2048..4096)

    // -------- load + transpose weights for this latent into SMEM --------
    {
        const int h = tid;  // 128 threads <-> 128 hidden units
        const float* w1r = W1 + (size_t)(d * 128 + h) * 65;
#pragma unroll
        for (int k = 0; k < 65; k++) sm[OFF_W1 + k * 128 + h] = w1r[k];

        const float* w2r = W2 + (size_t)(d * 128 + h) * 128;
        const float* w3r = W3 + (size_t)(d * 128 + h) * 128;
#pragma unroll
        for (int k4 = 0; k4 < 128; k4 += 4) {
            float4 v2 = *(const float4*)(w2r + k4);
            sm[OFF_W2 + (k4 + 0) * 128 + h] = v2.x;
            sm[OFF_W2 + (k4 + 1) * 128 + h] = v2.y;
            sm[OFF_W2 + (k4 + 2) * 128 + h] = v2.z;
            sm[OFF_W2 + (k4 + 3) * 128 + h] = v2.w;
            float4 v3 = *(const float4*)(w3r + k4);
            sm[OFF_W3 + (k4 + 0) * 128 + h] = v3.x;
            sm[OFF_W3 + (k4 + 1) * 128 + h] = v3.y;
            sm[OFF_W3 + (k4 + 2) * 128 + h] = v3.z;
            sm[OFF_W3 + (k4 + 3) * 128 + h] = v3.w;
        }
        sm[OFF_B1 + h] = b1[d * 128 + h];
        sm[OFF_B2 + h] = b2[d * 128 + h];
        sm[OFF_B3 + h] = b3[d * 128 + h];
        sm[OFF_W4 + h] = W4[d * 128 + h];
    }
    const float b4d = b4[d];
    __syncthreads();

    const int m0 = (tid & 7) * 4;   // 8 groups * 4 samples  = 32 m
    const int h0 = (tid >> 3) * 8;  // 16 groups * 8 hiddens = 128 h

    for (int tile = 0; tile < 64; tile++) {
        const int n0 = half * 2048 + tile * 32;
        const int b  = n0 >> 8;     // batch
        const int t0 = n0 & 255;    // time within batch

        // -------- stage input tile xl[k][m] (k<64: x[b,t,k]; k==64: x[b,t+1,d]) --------
        {
            float* xl = sm + OFF_BA1;  // BA1 is dead here; aliased as x-tile
            const int m = tid >> 2, part = tid & 3;
            const float* xr = x + ((size_t)(b * 257 + t0 + m)) * 64 + part * 16;
#pragma unroll
            for (int i = 0; i < 16; i += 4) {
                float4 v = *(const float4*)(xr + i);
                const int k = part * 16 + i;
                xl[(k + 0) * 32 + m] = v.x;
                xl[(k + 1) * 32 + m] = v.y;
                xl[(k + 2) * 32 + m] = v.z;
                xl[(k + 3) * 32 + m] = v.w;
            }
            if (tid < 32)
                xl[64 * 32 + tid] = x[((size_t)(b * 257 + t0 + tid + 1)) * 64 + d];
        }
        __syncthreads();

        // -------- Layer 1 (K=65, forward only) -> BA0 (a1), BD0 (d1 = s1 * W1[:,64]) --------
        {
            u64 accA[4][4];
#pragma unroll
            for (int i = 0; i < 4; i++)
#pragma unroll
                for (int j = 0; j < 4; j++) accA[i][j] = 0ull;

            const float* xl = sm + OFF_BA1;
            const float* Wt = sm + OFF_W1;
#pragma unroll 5
            for (int k = 0; k < 65; k++) {
                float4 av = *(const float4*)(xl + k * 32 + m0);
                ulonglong2 wA = *(const ulonglong2*)(Wt + k * 128 + h0);
                ulonglong2 wB = *(const ulonglong2*)(Wt + k * 128 + h0 + 4);
                u64 w[4] = { wA.x, wA.y, wB.x, wB.y };
                u64 a[4] = { dup2(av.x), dup2(av.y), dup2(av.z), dup2(av.w) };
#pragma unroll
                for (int m = 0; m < 4; m++)
#pragma unroll
                    for (int hp = 0; hp < 4; hp++)
                        accA[m][hp] = fma2(a[m], w[hp], accA[m][hp]);
            }
            float* Aout = sm + OFF_BA0;
            float* Dout = sm + OFF_BD0;
#pragma unroll
            for (int hp = 0; hp < 4; hp++) {
                const int hlo = h0 + 2 * hp, hhi = hlo + 1;
                const float blo = sm[OFF_B1 + hlo], bhi = sm[OFF_B1 + hhi];
                const float wclo = sm[OFF_W1 + 64 * 128 + hlo];
                const float wchi = sm[OFF_W1 + 64 * 128 + hhi];
                float alo[4], ahi[4], dlo[4], dhi[4];
#pragma unroll
                for (int m = 0; m < 4; m++) {
                    float2 pa = unpack2(accA[m][hp]);
                    float p0 = pa.x + blo; float s0 = (p0 > 0.f) ? 1.f : SLOPE;
                    alo[m] = p0 * s0;  dlo[m] = s0 * wclo;
                    float p1 = pa.y + bhi; float s1 = (p1 > 0.f) ? 1.f : SLOPE;
                    ahi[m] = p1 * s1;  dhi[m] = s1 * wchi;
                }
                *(float4*)(Aout + hlo * 32 + m0) = make_float4(alo[0], alo[1], alo[2], alo[3]);
                *(float4*)(Aout + hhi * 32 + m0) = make_float4(ahi[0], ahi[1], ahi[2], ahi[3]);
                *(float4*)(Dout + hlo * 32 + m0) = make_float4(dlo[0], dlo[1], dlo[2], dlo[3]);
                *(float4*)(Dout + hhi * 32 + m0) = make_float4(dhi[0], dhi[1], dhi[2], dhi[3]);
            }
        }
        __syncthreads();

        // -------- Layer 2 fused fwd+deriv: BA0/BD0 -> BA1/BD1 --------
        gemm_fused(sm, OFF_BA0, OFF_BD0, OFF_W2, OFF_B2, OFF_BA1, OFF_BD1, m0, h0);
        __syncthreads();

        // -------- Layer 3 fused fwd+deriv: BA1/BD1 -> BA0/BD0 --------
        gemm_fused(sm, OFF_BA1, OFF_BD1, OFF_W3, OFF_B3, OFF_BA0, OFF_BD0, m0, h0);
        __syncthreads();

        // -------- Layer 4 reductions: residual + log|deriv| --------
        {
            float* red = sm + OFF_BA1;  // scratch aliases BA1 (dead)
            const int m = tid & 31, q = tid >> 5;
            const float* A3 = sm + OFF_BA0;
            const float* D3 = sm + OFF_BD0;
            float pa = 0.f, pd = 0.f;
#pragma unroll
            for (int hh = 0; hh < 32; hh++) {
                const int h = q * 32 + hh;
                const float w = sm[OFF_W4 + h];
                pa += A3[h * 32 + m] * w;
                pd += D3[h * 32 + m] * w;
            }
            red[q * 32 + m]       = pa;
            red[128 + q * 32 + m] = pd;
            __syncthreads();
            if (tid < 32) {
                const int n = n0 + tid;
                float res = red[tid] + red[32 + tid] + red[64 + tid] + red[96 + tid] + b4d;
                out_res[(size_t)n * 64 + d] = res;
                float dv = red[128 + tid] + red[160 + tid] + red[192 + tid] + red[224 + tid];
                g_scratch[d * 4096 + n] = logf(fabsf(dv) + 1e-8f);
            }
        }
        __syncthreads();
    }
}

// deterministic sum over latents: out_logdet[n] = sum_d scratch[d][n]
__global__ void reduce_logdet_kernel(float* __restrict__ out_ld)
{
    const int n = blockIdx.x * blockDim.x + threadIdx.x;
    if (n < 4096) {
        float s = 0.f;
#pragma unroll
        for (int d = 0; d < 64; d++) s += g_scratch[d * 4096 + n];
        out_ld[n] = s;
    }
}

extern "C" void kernel_launch(void* const* d_in, const int* in_sizes, int n_in,
                              void* d_out, int out_size)
{
    const float* x  = (const float*)d_in[0];
    const float* W1 = (const float*)d_in[1];
    const float* b1 = (const float*)d_in[2];
    const float* W2 = (const float*)d_in[3];
    const float* b2 = (const float*)d_in[4];
    const float* W3 = (const float*)d_in[5];
    const float* b3 = (const float*)d_in[6];
    const float* W4 = (const float*)d_in[7];
    const float* b4 = (const float*)d_in[8];
    (void)in_sizes; (void)n_in; (void)out_size;

    float* out_res = (float*)d_out;                  // [16,256,64]
    float* out_ld  = (float*)d_out + 16 * 256 * 64;  // [16,256]

    const size_t smem = (size_t)SMEM_FLOATS * sizeof(float);  // 231,936 B
    cudaFuncSetAttribute(npt_kernel, cudaFuncAttributeMaxDynamicSharedMemorySize, (int)smem);

    npt_kernel<<<128, THREADS, smem>>>(x, W1, b1, W2, b2, W3, b3, W4, b4, out_res);
    reduce_logdet_kernel<<<16, 256>>>(out_ld);
}

// round 5
// speedup vs baseline: 1.0196x; 1.0196x over previous
#include <cuda_runtime.h>
#include <cstdint>

#define SLOPE 0.2f
#define THREADS 256

typedef unsigned long long u64;

// ---------------- packed f32x2 helpers (Blackwell FFMA2 path) ----------------
__device__ __forceinline__ u64 fma2(u64 a, u64 b, u64 c) {
    u64 d;
    asm("fma.rn.f32x2 %0, %1, %2, %3;" : "=l"(d) : "l"(a), "l"(b), "l"(c));
    return d;
}
__device__ __forceinline__ u64 dup2(float x) {
    u64 d;
    asm("mov.b64 %0, {%1, %1};" : "=l"(d) : "f"(x));
    return d;
}
__device__ __forceinline__ float2 unpack2(u64 v) {
    float2 r;
    asm("mov.b64 {%0, %1}, %2;" : "=f"(r.x), "=f"(r.y) : "l"(v));
    return r;
}

// ---------------- shared memory layout (float offsets) ----------------
// Weights transposed: Wt[k*128 + h] = W[h][k]
#define OFF_W1   0                       // [65][128]
#define OFF_W2   (65*128)                // [128][128]
#define OFF_W3   (OFF_W2 + 128*128)      // [128][128]
#define OFF_B1   (OFF_W3 + 128*128)
#define OFF_B2   (OFF_B1 + 128)
#define OFF_B3   (OFF_B2 + 128)
#define OFF_W4   (OFF_B3 + 128)
#define OFF_BA0  (OFF_W4 + 128)          // [128][32] activation ping
#define OFF_BD0  (OFF_BA0 + 128*32)      // [128][32] deriv ping
#define OFF_BA1  (OFF_BD0 + 128*32)      // [128][32] activation pong (aliases x-tile & reduce scratch)
#define OFF_BD1  (OFF_BA1 + 128*32)      // [128][32] deriv pong
#define SMEM_FLOATS (OFF_BD1 + 128*32)   // 57,984 floats = 231,936 B  (< 232,448 cap)

// deterministic cross-d logdet partials: scratch[d][n]
__device__ float g_scratch[64 * 4096];

// Fused forward + derivative GEMM over one layer (256-thread variant):
//   each thread: 4 samples (m0..m0+3) x 4 hidden (h0..h0+3)
//   accA[h] = sum_k Wt[k][h] * Ain[k][m]      (then p = accA + b, s = slope(p))
//   accD[h] = sum_k Wt[k][h] * Din[k][m]      (then Dout = s * accD, Aout = p*s)
__device__ __forceinline__ void gemm_fused(
    float* sm, int offAin, int offDin, int offW, int offB,
    int offAout, int offDout, int m0, int h0)
{
    u64 accA[4][2], accD[4][2];
#pragma unroll
    for (int i = 0; i < 4; i++)
#pragma unroll
        for (int j = 0; j < 2; j++) { accA[i][j] = 0ull; accD[i][j] = 0ull; }

    const float* Ain = sm + offAin;
    const float* Din = sm + offDin;
    const float* Wt  = sm + offW;

#pragma unroll 4
    for (int k = 0; k < 128; k++) {
        float4 av = *(const float4*)(Ain + k * 32 + m0);
        float4 dv = *(const float4*)(Din + k * 32 + m0);
        ulonglong2 wv = *(const ulonglong2*)(Wt + k * 128 + h0);
        u64 w[2]  = { wv.x, wv.y };
        u64 a[4]  = { dup2(av.x), dup2(av.y), dup2(av.z), dup2(av.w) };
        u64 dd[4] = { dup2(dv.x), dup2(dv.y), dup2(dv.z), dup2(dv.w) };
#pragma unroll
        for (int m = 0; m < 4; m++)
#pragma unroll
            for (int hp = 0; hp < 2; hp++) {
                accA[m][hp] = fma2(a[m],  w[hp], accA[m][hp]);
                accD[m][hp] = fma2(dd[m], w[hp], accD[m][hp]);
            }
    }

    float* Aout = sm + offAout;
    float* Dout = sm + offDout;
#pragma unroll
    for (int hp = 0; hp < 2; hp++) {
        const int hlo = h0 + 2 * hp, hhi = hlo + 1;
        const float blo = sm[offB + hlo];
        const float bhi = sm[offB + hhi];
        float alo[4], ahi[4], dlo[4], dhi[4];
#pragma unroll
        for (int m = 0; m < 4; m++) {
            float2 pa = unpack2(accA[m][hp]);
            float2 pd = unpack2(accD[m][hp]);
            float p0 = pa.x + blo; float s0 = (p0 > 0.f) ? 1.f : SLOPE;
            alo[m] = p0 * s0;  dlo[m] = s0 * pd.x;
            float p1 = pa.y + bhi; float s1 = (p1 > 0.f) ? 1.f : SLOPE;
            ahi[m] = p1 * s1;  dhi[m] = s1 * pd.y;
        }
        *(float4*)(Aout + hlo * 32 + m0) = make_float4(alo[0], alo[1], alo[2], alo[3]);
        *(float4*)(Aout + hhi * 32 + m0) = make_float4(ahi[0], ahi[1], ahi[2], ahi[3]);
        *(float4*)(Dout + hlo * 32 + m0) = make_float4(dlo[0], dlo[1], dlo[2], dlo[3]);
        *(float4*)(Dout + hhi * 32 + m0) = make_float4(dhi[0], dhi[1], dhi[2], dhi[3]);
    }
}

__global__ void __launch_bounds__(THREADS, 1)
npt_kernel(const float* __restrict__ x,
           const float* __restrict__ W1, const float* __restrict__ b1,
           const float* __restrict__ W2, const float* __restrict__ b2,
           const float* __restrict__ W3, const float* __restrict__ b3,
           const float* __restrict__ W4, const float* __restrict__ b4,
           float* __restrict__ out_res)
{
    extern __shared__ float sm[];
    const int tid  = threadIdx.x;
    const int d    = blockIdx.x >> 1;   // latent index
    const int half = blockIdx.x & 1;    // sample half [0..2048) / [2048..4096)

    // -------- load + transpose weights for this latent into SMEM (256 threads) --------
    {
        const int h  = tid & 127;  // hidden unit
        const int hf = tid >> 7;   // k-range half (0/1)

        // W1: hf=0 -> k in [0,33), hf=1 -> k in [33,65)
        const float* w1r = W1 + (size_t)(d * 128 + h) * 65;
        const int kbeg = hf ? 33 : 0;
        const int kend = hf ? 65 : 33;
        for (int k = kbeg; k < kend; k++) sm[OFF_W1 + k * 128 + h] = w1r[k];

        // W2/W3: hf=0 -> k in [0,64), hf=1 -> k in [64,128)
        const float* w2r = W2 + (size_t)(d * 128 + h) * 128;
        const float* w3r = W3 + (size_t)(d * 128 + h) * 128;
        const int k0 = hf * 64;
#pragma unroll
        for (int kk = 0; kk < 64; kk += 4) {
            const int k4 = k0 + kk;
            float4 v2 = *(const float4*)(w2r + k4);
            sm[OFF_W2 + (k4 + 0) * 128 + h] = v2.x;
            sm[OFF_W2 + (k4 + 1) * 128 + h] = v2.y;
            sm[OFF_W2 + (k4 + 2) * 128 + h] = v2.z;
            sm[OFF_W2 + (k4 + 3) * 128 + h] = v2.w;
            float4 v3 = *(const float4*)(w3r + k4);
            sm[OFF_W3 + (k4 + 0) * 128 + h] = v3.x;
            sm[OFF_W3 + (k4 + 1) * 128 + h] = v3.y;
            sm[OFF_W3 + (k4 + 2) * 128 + h] = v3.z;
            sm[OFF_W3 + (k4 + 3) * 128 + h] = v3.w;
        }
        if (hf == 0) {
            sm[OFF_B1 + h] = b1[d * 128 + h];
            sm[OFF_B2 + h] = b2[d * 128 + h];
            sm[OFF_B3 + h] = b3[d * 128 + h];
            sm[OFF_W4 + h] = W4[d * 128 + h];
        }
    }
    const float b4d = b4[d];
    __syncthreads();

    const int m0 = (tid & 7) * 4;   // 8 groups * 4 samples  = 32 m
    const int h0 = (tid >> 3) * 4;  // 32 groups * 4 hiddens = 128 h

    for (int tile = 0; tile < 64; tile++) {
        const int n0 = half * 2048 + tile * 32;
        const int b  = n0 >> 8;     // batch
        const int t0 = n0 & 255;    // time within batch

        // -------- stage input tile xl[k][m] (k<64: x[b,t,k]; k==64: x[b,t+1,d]) --------
        {
            float* xl = sm + OFF_BA1;  // BA1 is dead here; aliased as x-tile
            const int m = tid >> 3, part = tid & 7;   // 32 m rows x 8 threads x 8 floats
            const float* xr = x + ((size_t)(b * 257 + t0 + m)) * 64 + part * 8;
#pragma unroll
            for (int i = 0; i < 8; i += 4) {
                float4 v = *(const float4*)(xr + i);
                const int k = part * 8 + i;
                xl[(k + 0) * 32 + m] = v.x;
                xl[(k + 1) * 32 + m] = v.y;
                xl[(k + 2) * 32 + m] = v.z;
                xl[(k + 3) * 32 + m] = v.w;
            }
            if (tid < 32)
                xl[64 * 32 + tid] = x[((size_t)(b * 257 + t0 + tid + 1)) * 64 + d];
        }
        __syncthreads();

        // -------- Layer 1 (K=65, forward only) -> BA0 (a1), BD0 (d1 = s1 * W1[:,64]) --------
        {
            u64 accA[4][2];
#pragma unroll
            for (int i = 0; i < 4; i++)
#pragma unroll
                for (int j = 0; j < 2; j++) accA[i][j] = 0ull;

            const float* xl = sm + OFF_BA1;
            const float* Wt = sm + OFF_W1;
#pragma unroll 5
            for (int k = 0; k < 65; k++) {
                float4 av = *(const float4*)(xl + k * 32 + m0);
                ulonglong2 wv = *(const ulonglong2*)(Wt + k * 128 + h0);
                u64 w[2] = { wv.x, wv.y };
                u64 a[4] = { dup2(av.x), dup2(av.y), dup2(av.z), dup2(av.w) };
#pragma unroll
                for (int m = 0; m < 4; m++)
#pragma unroll
                    for (int hp = 0; hp < 2; hp++)
                        accA[m][hp] = fma2(a[m], w[hp], accA[m][hp]);
            }
            float* Aout = sm + OFF_BA0;
            float* Dout = sm + OFF_BD0;
#pragma unroll
            for (int hp = 0; hp < 2; hp++) {
                const int hlo = h0 + 2 * hp, hhi = hlo + 1;
                const float blo = sm[OFF_B1 + hlo], bhi = sm[OFF_B1 + hhi];
                const float wclo = sm[OFF_W1 + 64 * 128 + hlo];
                const float wchi = sm[OFF_W1 + 64 * 128 + hhi];
                float alo[4], ahi[4], dlo[4], dhi[4];
#pragma unroll
                for (int m = 0; m < 4; m++) {
                    float2 pa = unpack2(accA[m][hp]);
                    float p0 = pa.x + blo; float s0 = (p0 > 0.f) ? 1.f : SLOPE;
                    alo[m] = p0 * s0;  dlo[m] = s0 * wclo;
                    float p1 = pa.y + bhi; float s1 = (p1 > 0.f) ? 1.f : SLOPE;
                    ahi[m] = p1 * s1;  dhi[m] = s1 * wchi;
                }
                *(float4*)(Aout + hlo * 32 + m0) = make_float4(alo[0], alo[1], alo[2], alo[3]);
                *(float4*)(Aout + hhi * 32 + m0) = make_float4(ahi[0], ahi[1], ahi[2], ahi[3]);
                *(float4*)(Dout + hlo * 32 + m0) = make_float4(dlo[0], dlo[1], dlo[2], dlo[3]);
                *(float4*)(Dout + hhi * 32 + m0) = make_float4(dhi[0], dhi[1], dhi[2], dhi[3]);
            }
        }
        __syncthreads();

        // -------- Layer 2 fused fwd+deriv: BA0/BD0 -> BA1/BD1 --------
        gemm_fused(sm, OFF_BA0, OFF_BD0, OFF_W2, OFF_B2, OFF_BA1, OFF_BD1, m0, h0);
        __syncthreads();

        // -------- Layer 3 fused fwd+deriv: BA1/BD1 -> BA0/BD0 --------
        gemm_fused(sm, OFF_BA1, OFF_BD1, OFF_W3, OFF_B3, OFF_BA0, OFF_BD0, m0, h0);
        __syncthreads();

        // -------- Layer 4 reductions: residual + log|deriv| --------
        {
            float* red = sm + OFF_BA1;  // scratch aliases BA1 (dead)
            const int m = tid & 31, q = tid >> 5;   // 8 groups x 16 h each
            const float* A3 = sm + OFF_BA0;
            const float* D3 = sm + OFF_BD0;
            float pa = 0.f, pd = 0.f;
#pragma unroll
            for (int hh = 0; hh < 16; hh++) {
                const int h = q * 16 + hh;
                const float w = sm[OFF_W4 + h];
                pa += A3[h * 32 + m] * w;
                pd += D3[h * 32 + m] * w;
            }
            red[q * 32 + m]       = pa;
            red[256 + q * 32 + m] = pd;
            __syncthreads();
            if (tid < 32) {
                const int n = n0 + tid;
                float res = b4d;
                float dv  = 0.f;
#pragma unroll
                for (int q2 = 0; q2 < 8; q2++) {
                    res += red[q2 * 32 + tid];
                    dv  += red[256 + q2 * 32 + tid];
                }
                out_res[(size_t)n * 64 + d] = res;
                g_scratch[d * 4096 + n] = logf(fabsf(dv) + 1e-8f);
            }
        }
        __syncthreads();
    }
}

// deterministic sum over latents: out_logdet[n] = sum_d scratch[d][n]
__global__ void reduce_logdet_kernel(float* __restrict__ out_ld)
{
    const int n = blockIdx.x * blockDim.x + threadIdx.x;
    if (n < 4096) {
        float s = 0.f;
#pragma unroll
        for (int d = 0; d < 64; d++) s += g_scratch[d * 4096 + n];
        out_ld[n] = s;
    }
}

extern "C" void kernel_launch(void* const* d_in, const int* in_sizes, int n_in,
                              void* d_out, int out_size)
{
    const float* x  = (const float*)d_in[0];
    const float* W1 = (const float*)d_in[1];
    const float* b1 = (const float*)d_in[2];
    const float* W2 = (const float*)d_in[3];
    const float* b2 = (const float*)d_in[4];
    const float* W3 = (const float*)d_in[5];
    const float* b3 = (const float*)d_in[6];
    const float* W4 = (const float*)d_in[7];
    const float* b4 = (const float*)d_in[8];
    (void)in_sizes; (void)n_in; (void)out_size;

    float* out_res = (float*)d_out;                  // [16,256,64]
    float* out_ld  = (float*)d_out + 16 * 256 * 64;  // [16,256]

    const size_t smem = (size_t)SMEM_FLOATS * sizeof(float);  // 231,936 B
    cudaFuncSetAttribute(npt_kernel, cudaFuncAttributeMaxDynamicSharedMemorySize, (int)smem);

    npt_kernel<<<128, THREADS, smem>>>(x, W1, b1, W2, b2, W3, b3, W4, b4, out_res);
    reduce_logdet_kernel<<<16, 256>>>(out_ld);
}